// round 7
// baseline (speedup 1.0000x reference)
#include <cuda_runtime.h>
#include <math.h>

// GraphQNN: 22-qubit real-amplitude state-vector simulation.
// R7: 64-bit shared-memory ops via one-bit view overlap.
//  passL views: A{0-4,pair=4} B{4,5-8: LDS.64/STS.64, packed-only} C{9-13}.
//    layout y = x4 | (x0-3)<<1 | (x5-13)<<5, swizzle y^(((y>>5)&15)<<1).
//  passHH/passH1: exchange layout u = h3 | tl<<1 | ... -> all exchange
//    traffic STS.64/LDS.64 (pairs along h3, which both views hold).
// Sweep structure (5 sweeps) unchanged from R5/R6.

#define NQ 22
#define DIM (1 << NQ)
#define LOWB 14
#define LOWDIM (1 << LOWB)
#define FULL 0xffffffffu
typedef unsigned long long ull;

__device__ float g_state[DIM];
__device__ float g_c[4][NQ];   // [stage][bitpos] stage0 = features, 1..3 = layers
__device__ float g_s[4][NQ];
__device__ unsigned g_pm[NQ];  // per bit position: mask of paired bit positions

__device__ __forceinline__ unsigned par(unsigned v) {
    return (unsigned)__popc(v) & 1u;
}

// ---------------------------------------------------------------- f32x2
__device__ __forceinline__ ull pk2(float x, float y) {
    ull r; asm("mov.b64 %0, {%1,%2};" : "=l"(r) : "f"(x), "f"(y)); return r;
}
__device__ __forceinline__ float2 upk2(ull v) {
    float2 f; asm("mov.b64 {%0,%1}, %2;" : "=f"(f.x), "=f"(f.y) : "l"(v)); return f;
}
__device__ __forceinline__ ull mul2_(ull a, ull b) {
    ull r; asm("mul.rn.f32x2 %0, %1, %2;" : "=l"(r) : "l"(a), "l"(b)); return r;
}
__device__ __forceinline__ ull fma2_(ull a, ull b, ull c) {
    ull r; asm("fma.rn.f32x2 %0, %1, %2, %3;" : "=l"(r) : "l"(a), "l"(b), "l"(c)); return r;
}

// butterfly on 32 elements held as 16 pairs.
// BIT = 0: pair-internal (scalar). BIT>=1: packed across pair index bit BIT-1.
template <int BIT>
__device__ __forceinline__ void bflyp(ull* p, float c, float s) {
    if (BIT == 0) {
#pragma unroll
        for (int i = 0; i < 16; i++) {
            float2 v = upk2(p[i]);
            p[i] = pk2(fmaf(c, v.x, -(s * v.y)), fmaf(s, v.x, c * v.y));
        }
    } else {
        const ull cc = pk2(c, c), ss = pk2(s, s), ns = pk2(-s, -s);
#pragma unroll
        for (int i0 = 0; i0 < 16; i0++) {
            if ((i0 & (1 << (BIT - 1))) == 0) {
                int i1 = i0 | (1 << (BIT - 1));
                ull v0 = p[i0], v1 = p[i1];
                p[i0] = fma2_(cc, v0, mul2_(ns, v1));
                p[i1] = fma2_(ss, v0, mul2_(cc, v1));
            }
        }
    }
}

// ---------------------------------------------------------------- setup
__global__ void k_setup(const float* __restrict__ feat,
                        const float* __restrict__ adj,
                        const float* __restrict__ params,
                        float* __restrict__ out) {
    int t = threadIdx.x;
    if (t < 4 * NQ) {
        int s = t / NQ;
        int b = t % NQ;
        int q = NQ - 1 - b;
        float th = (s == 0 ? feat[q] : params[(s - 1) * NQ + q]) * 0.5f;
        g_c[s][b] = cosf(th);
        g_s[s][b] = sinf(th);
    }
    if (t < NQ) {
        int q = NQ - 1 - t;
        unsigned m = 0;
        for (int qq = 0; qq < NQ; qq++) {
            if (qq == q) continue;
            int i = q < qq ? q : qq;
            int j = q < qq ? qq : q;
            if (adj[i * NQ + j] > 0.0f) m |= (1u << (NQ - 1 - qq));
        }
        g_pm[t] = m;
        out[t] = 0.0f;
    }
}

__device__ __forceinline__ unsigned signB(unsigned ulow) {
    unsigned Bb = 0;
#pragma unroll
    for (int a = 1; a < LOWB; a++)
        Bb ^= ((ulow >> a) & 1u) & par(ulow & g_pm[a] & ((1u << a) - 1u));
    return Bb;
}
__device__ __forceinline__ unsigned signCL(unsigned ulow) {
    unsigned cl = 0;
#pragma unroll
    for (int j = 0; j < 8; j++)
        cl |= par(ulow & g_pm[14 + j] & 0x3FFFu) << j;
    return cl;
}

// Mapping helpers for H passes (pairs along h3):
// pair j (j0-2 = h0-2, j3 = h4): klo = h index with h3=0.
__device__ __forceinline__ int hklo(int j) { return (j & 7) | ((j >> 3) << 4); }

// ---------------------------------------------------------------- K2 passHH
// bits 14..21, two layers fused. Tile 256 h x 64 low. 512 thr x 32.
// View A: regs k = h0-4 (pairs along h3), hv = h5-7.
// View B: regs k = h3-7 (pairs along h3), hv = h0-2.
// Exchange layout u = h3 | tl<<1 | (h0-2)<<7 | h4<<10 | (h5-7)<<11 (all 64-bit).
template <int S1, int S2>
__global__ void __launch_bounds__(512, 2) k_passHH() {
    extern __shared__ float sm[];   // 16384 floats
    const int t = threadIdx.x;
    const int lane = t & 31;
    float c1 = lane < NQ ? g_c[S1][lane] : 0.f;
    float s1 = lane < NQ ? g_s[S1][lane] : 0.f;
    float c2 = lane < NQ ? g_c[S2][lane] : 0.f;
    float s2 = lane < NQ ? g_s[S2][lane] : 0.f;
#define CF1(b) __shfl_sync(FULL, c1, (b))
#define SF1(b) __shfl_sync(FULL, s1, (b))
#define CF2(b) __shfl_sync(FULL, c2, (b))
#define SF2(b) __shfl_sync(FULL, s2, (b))

    const int tl = t & 63;
    const unsigned hv = t >> 6;          // h5-7 in view A, h0-2 in view B
    const int low = (blockIdx.x << 6) + tl;
    const unsigned ulow = (unsigned)low;

    // ---- sign constants for VIEW B: h = hv | h3<<3 | i<<4, k = h3|(i<<1)
    unsigned Bb = signB(ulow);
    unsigned cl = signCL(ulow);
    unsigned Alo = 0;
#pragma unroll
    for (int a = 1; a < 3; a++)
        Alo ^= ((hv >> a) & 1u) & par(hv & ((g_pm[14 + a] >> 14) & ((1u << a) - 1u)));
    unsigned cm = 0;
#pragma unroll
    for (int i = 0; i < 5; i++)
        cm |= par(hv & ((g_pm[17 + i] >> 14) & 7u)) << i;
    const unsigned km = ((cl >> 3) & 31u) ^ cm;
    const unsigned cbase = Bb ^ par(hv & (cl & 7u)) ^ Alo;
    unsigned ab = 0;
#pragma unroll
    for (int i = 1; i < 5; i++)
        ab ^= (((unsigned)lane >> i) & 1u) &
              par((unsigned)lane & ((g_pm[17 + i] >> 17) & ((1u << i) - 1u)));
    const unsigned akk = __ballot_sync(FULL, ab);

    ull p[16];
    // ---- view A load, pairs along h3
#pragma unroll
    for (int j = 0; j < 16; j++) {
        int klo = hklo(j);
        p[j] = pk2(g_state[(((hv << 5) | klo) << LOWB) | low],
                   g_state[(((hv << 5) | klo | 8) << LOWB) | low]);
    }

    // stage S1 bits 14-18: internal h3(17); packed h0(14),h1(15),h2(16),h4(18)
    bflyp<0>(p, CF1(17), SF1(17));
    bflyp<1>(p, CF1(14), SF1(14));
    bflyp<2>(p, CF1(15), SF1(15));
    bflyp<3>(p, CF1(16), SF1(16));
    bflyp<4>(p, CF1(18), SF1(18));

    // exchange A -> B (STS.64)
#pragma unroll
    for (int j = 0; j < 16; j++) {
        int u = (tl << 1) | ((j & 7) << 7) | ((j >> 3) << 10) | (hv << 11);
        *reinterpret_cast<ull*>(&sm[u]) = p[j];
    }
    __syncthreads();
#pragma unroll
    for (int i = 0; i < 16; i++) {
        int u = (tl << 1) | (hv << 7) | ((i & 1) << 10) | ((i >> 1) << 11);
        p[i] = *reinterpret_cast<const ull*>(&sm[u]);
    }

    // stage S1 bits 19-21 (i bits 1-3)
    bflyp<2>(p, CF1(19), SF1(19));
    bflyp<3>(p, CF1(20), SF1(20));
    bflyp<4>(p, CF1(21), SF1(21));

    // ---- diagonal sign (k = 2i lo, 2i+1 hi)
#pragma unroll
    for (int i = 0; i < 16; i++) {
        unsigned lo = cbase ^ ((akk >> (2 * i)) & 1u) ^ par((unsigned)(2 * i) & km);
        unsigned hi = cbase ^ ((akk >> (2 * i + 1)) & 1u) ^ par((unsigned)(2 * i + 1) & km);
        p[i] ^= ((ull)hi << 63) | ((ull)lo << 31);
    }

    // stage S2 bits 19-21
    bflyp<2>(p, CF2(19), SF2(19));
    bflyp<3>(p, CF2(20), SF2(20));
    bflyp<4>(p, CF2(21), SF2(21));

    // exchange B -> A (in-place write set == read set; STS.64 then LDS.64)
#pragma unroll
    for (int i = 0; i < 16; i++) {
        int u = (tl << 1) | (hv << 7) | ((i & 1) << 10) | ((i >> 1) << 11);
        *reinterpret_cast<ull*>(&sm[u]) = p[i];
    }
    __syncthreads();
#pragma unroll
    for (int j = 0; j < 16; j++) {
        int u = (tl << 1) | ((j & 7) << 7) | ((j >> 3) << 10) | (hv << 11);
        p[j] = *reinterpret_cast<const ull*>(&sm[u]);
    }

    // stage S2 bits 14-18
    bflyp<0>(p, CF2(17), SF2(17));
    bflyp<1>(p, CF2(14), SF2(14));
    bflyp<2>(p, CF2(15), SF2(15));
    bflyp<3>(p, CF2(16), SF2(16));
    bflyp<4>(p, CF2(18), SF2(18));

#pragma unroll
    for (int j = 0; j < 16; j++) {
        float2 v = upk2(p[j]);
        int klo = hklo(j);
        g_state[(((hv << 5) | klo) << LOWB) | low] = v.x;
        g_state[(((hv << 5) | klo | 8) << LOWB) | low] = v.y;
    }
#undef CF1
#undef SF1
#undef CF2
#undef SF2
}

// ---------------------------------------------------------------- K4 passH1
// sign at load (view A: h = (hv<<5)|k) + stage S hi RYs.
template <int S>
__global__ void __launch_bounds__(512, 2) k_passH1() {
    extern __shared__ float sm[];
    const int t = threadIdx.x;
    const int lane = t & 31;
    float myc = lane < NQ ? g_c[S][lane] : 0.f;
    float mys = lane < NQ ? g_s[S][lane] : 0.f;
#define CF(b) __shfl_sync(FULL, myc, (b))
#define SF(b) __shfl_sync(FULL, mys, (b))

    const int tl = t & 63;
    const unsigned hv = t >> 6;          // h5-7
    const int low = (blockIdx.x << 6) + tl;
    const unsigned ulow = (unsigned)low;

    // ---- sign constants for VIEW A: k bits = global 14-18
    unsigned Bb = signB(ulow);
    unsigned cl = signCL(ulow);
    unsigned chm = 0;
#pragma unroll
    for (int a = 0; a < 5; a++)
        chm |= par(hv & ((g_pm[14 + a] >> 19) & 7u)) << a;
    unsigned Ahh = 0;
#pragma unroll
    for (int a = 1; a < 3; a++)
        Ahh ^= ((hv >> a) & 1u) & par(hv & ((g_pm[19 + a] >> 19) & ((1u << a) - 1u)));
    unsigned ab = 0;
#pragma unroll
    for (int a = 1; a < 5; a++)
        ab ^= (((unsigned)lane >> a) & 1u) &
              par((unsigned)lane & ((g_pm[14 + a] >> 14) & ((1u << a) - 1u)));
    const unsigned akk = __ballot_sync(FULL, ab);
    const unsigned km = (cl & 31u) ^ chm;
    const unsigned cbase = Bb ^ par(hv & (cl >> 5)) ^ Ahh;

    ull p[16];
#pragma unroll
    for (int j = 0; j < 16; j++) {
        int klo = hklo(j);
        p[j] = pk2(g_state[(((hv << 5) | klo) << LOWB) | low],
                   g_state[(((hv << 5) | klo | 8) << LOWB) | low]);
    }
#pragma unroll
    for (int j = 0; j < 16; j++) {
        unsigned klo = (unsigned)hklo(j), khi = klo | 8u;
        unsigned lo = cbase ^ ((akk >> klo) & 1u) ^ par(klo & km);
        unsigned hi = cbase ^ ((akk >> khi) & 1u) ^ par(khi & km);
        p[j] ^= ((ull)hi << 63) | ((ull)lo << 31);
    }

    // stage S bits 14-18
    bflyp<0>(p, CF(17), SF(17));
    bflyp<1>(p, CF(14), SF(14));
    bflyp<2>(p, CF(15), SF(15));
    bflyp<3>(p, CF(16), SF(16));
    bflyp<4>(p, CF(18), SF(18));

    // exchange A -> B
#pragma unroll
    for (int j = 0; j < 16; j++) {
        int u = (tl << 1) | ((j & 7) << 7) | ((j >> 3) << 10) | (hv << 11);
        *reinterpret_cast<ull*>(&sm[u]) = p[j];
    }
    __syncthreads();
#pragma unroll
    for (int i = 0; i < 16; i++) {
        int u = (tl << 1) | (hv << 7) | ((i & 1) << 10) | ((i >> 1) << 11);
        p[i] = *reinterpret_cast<const ull*>(&sm[u]);
    }

    // stage S bits 19-21 (i bits 1-3)
    bflyp<2>(p, CF(19), SF(19));
    bflyp<3>(p, CF(20), SF(20));
    bflyp<4>(p, CF(21), SF(21));

    // store from view B: h = hv | h3<<3 | i<<4
#pragma unroll
    for (int i = 0; i < 16; i++) {
        float2 v = upk2(p[i]);
        g_state[((hv | (i << 4)) << LOWB) | low] = v.x;
        g_state[((hv | 8u | (i << 4)) << LOWB) | low] = v.y;
    }
#undef CF
#undef SF
}

// ---------------------------------------------------------------- pass L
// bits 0..13. Views: A{0-4, pair=x4} B{x4,5-8} C{9-13, pair=x9}.
// Layout y = x4 | (x0-3)<<1 | (x5-13)<<5, swizzle bits1-4 ^= bits5-8.
__device__ __forceinline__ int lw2(int y) { return y ^ (((y >> 5) & 15) << 1); }

template <int STAGE, bool INIT, bool LAST>
__global__ void __launch_bounds__(512, 2) k_passL(float* __restrict__ out) {
    extern __shared__ float sm[];
    __shared__ float acc[NQ];
    const int t = threadIdx.x;
    const int lane = t & 31;
    const int base = blockIdx.x << LOWB;
    float myc = lane < NQ ? g_c[STAGE][lane] : 0.f;
    float mys = lane < NQ ? g_s[STAGE][lane] : 0.f;
#define CF(b) __shfl_sync(FULL, myc, (b))
#define SF(b) __shfl_sync(FULL, mys, (b))
    ull p[16];

    if (LAST && t < NQ) acc[t] = 0.0f;

    if (INIT) {
        float c0 = lane < NQ ? g_c[0][lane] : 0.f;
        float s0 = lane < NQ ? g_s[0][lane] : 0.f;
        float a = 1.0f;
        const unsigned blk = blockIdx.x;     // bits 14-21
#pragma unroll
        for (int b = 0; b < 8; b++) {
            float cb = __shfl_sync(FULL, c0, 14 + b);
            float sb = __shfl_sync(FULL, s0, 14 + b);
            a *= ((blk >> b) & 1) ? sb : cb;
        }
#pragma unroll
        for (int b = 0; b < 9; b++) {        // bits 5-13 = t
            float cb = __shfl_sync(FULL, c0, 5 + b);
            float sb = __shfl_sync(FULL, s0, 5 + b);
            a *= ((t >> b) & 1) ? sb : cb;
        }
        float pc[5], ps[5];
#pragma unroll
        for (int b = 0; b < 5; b++) {
            pc[b] = __shfl_sync(FULL, c0, b);
            ps[b] = __shfl_sync(FULL, s0, b);
        }
        // pairs along x4: p[j] = (bits0-3 = j, x4 = 0/1)
#pragma unroll
        for (int j = 0; j < 16; j++) {
            float aj = a;
#pragma unroll
            for (int b = 0; b < 4; b++)
                aj *= ((j >> b) & 1) ? ps[b] : pc[b];
            p[j] = pk2(aj * pc[4], aj * ps[4]);
        }
    } else {
        // x = (t<<5)|m, m = 0..31; pairs (m, m|16) along x4
        float v[32];
        const float4* gp = reinterpret_cast<const float4*>(&g_state[base + t * 32]);
#pragma unroll
        for (int i = 0; i < 8; i++) {
            float4 q = gp[i];
            v[4 * i] = q.x; v[4 * i + 1] = q.y;
            v[4 * i + 2] = q.z; v[4 * i + 3] = q.w;
        }
#pragma unroll
        for (int j = 0; j < 16; j++)
            p[j] = pk2(v[j], v[j | 16]);
    }

    // ---- A: internal x4; packed x0-3
    bflyp<0>(p, CF(4), SF(4));
    bflyp<1>(p, CF(0), SF(0));
    bflyp<2>(p, CF(1), SF(1));
    bflyp<3>(p, CF(2), SF(2));
    bflyp<4>(p, CF(3), SF(3));

    // A store: y = (j<<1) | (t<<5)   (STS.64)
#pragma unroll
    for (int j = 0; j < 16; j++)
        *reinterpret_cast<ull*>(&sm[lw2((j << 1) | (t << 5))]) = p[j];
    __syncthreads();

    // ---- B: internal x4 (retired); packed x5-8 = i. Fixed x0-3 = t&15, x9-13 = t>>4.
    {
        const int yb = ((t & 15) << 1) | ((t >> 4) << 9);
#pragma unroll
        for (int i = 0; i < 16; i++)
            p[i] = *reinterpret_cast<const ull*>(&sm[lw2(yb | (i << 5))]);

        bflyp<1>(p, CF(5), SF(5));
        bflyp<2>(p, CF(6), SF(6));
        bflyp<3>(p, CF(7), SF(7));
        bflyp<4>(p, CF(8), SF(8));

#pragma unroll
        for (int i = 0; i < 16; i++)
            *reinterpret_cast<ull*>(&sm[lw2(yb | (i << 5))]) = p[i];
    }
    __syncthreads();

    // ---- C: internal x9; packed x10-13 = i. Fixed x0-8 = t.
    const int yc = ((t >> 4) & 1) | ((t & 15) << 1) | (((t >> 5) & 15) << 5);
#pragma unroll
    for (int i = 0; i < 16; i++)
        p[i] = pk2(sm[lw2(yc | ((2 * i) << 9))],
                   sm[lw2(yc | ((2 * i + 1) << 9))]);

    bflyp<0>(p, CF(9),  SF(9));
    bflyp<1>(p, CF(10), SF(10));
    bflyp<2>(p, CF(11), SF(11));
    bflyp<3>(p, CF(12), SF(12));
    bflyp<4>(p, CF(13), SF(13));

    if (!LAST) {
#pragma unroll
        for (int i = 0; i < 16; i++) {
            float2 v = upk2(p[i]);
            g_state[base | ((2 * i) << 9) | t] = v.x;
            g_state[base | ((2 * i + 1) << 9) | t] = v.y;
        }
    } else {
        // fused expvals. x bits: 0-4 lane, 5-8 warp, 9 pair, 10-13 i, 14-21 blk.
        float P = 0.f, S0 = 0.f, S1 = 0.f, S2 = 0.f, S3 = 0.f, S4 = 0.f;
#pragma unroll
        for (int i = 0; i < 16; i++) {
            float2 v = upk2(p[i]);
            float px = v.x * v.x, py = v.y * v.y;
            float pp = px + py;
            P += pp;
            S0 += px - py;                 // bit 9
            S1 += (i & 1) ? -pp : pp;      // bit 10
            S2 += (i & 2) ? -pp : pp;      // bit 11
            S3 += (i & 4) ? -pp : pp;      // bit 12
            S4 += (i & 8) ? -pp : pp;      // bit 13
        }
        float R0 = (lane & 1)  ? -P : P;
        float R1 = (lane & 2)  ? -P : P;
        float R2 = (lane & 4)  ? -P : P;
        float R3 = (lane & 8)  ? -P : P;
        float R4 = (lane & 16) ? -P : P;
#pragma unroll
        for (int o = 16; o; o >>= 1) {
            P  += __shfl_xor_sync(FULL, P, o);
            S0 += __shfl_xor_sync(FULL, S0, o);
            S1 += __shfl_xor_sync(FULL, S1, o);
            S2 += __shfl_xor_sync(FULL, S2, o);
            S3 += __shfl_xor_sync(FULL, S3, o);
            S4 += __shfl_xor_sync(FULL, S4, o);
            R0 += __shfl_xor_sync(FULL, R0, o);
            R1 += __shfl_xor_sync(FULL, R1, o);
            R2 += __shfl_xor_sync(FULL, R2, o);
            R3 += __shfl_xor_sync(FULL, R3, o);
            R4 += __shfl_xor_sync(FULL, R4, o);
        }
        if (lane == 0) {
            int wrp = t >> 5;
            atomicAdd(&acc[0], R0);
            atomicAdd(&acc[1], R1);
            atomicAdd(&acc[2], R2);
            atomicAdd(&acc[3], R3);
            atomicAdd(&acc[4], R4);
#pragma unroll
            for (int b = 5; b < 9; b++)
                atomicAdd(&acc[b], ((wrp >> (b - 5)) & 1) ? -P : P);
            atomicAdd(&acc[9],  S0);
            atomicAdd(&acc[10], S1);
            atomicAdd(&acc[11], S2);
            atomicAdd(&acc[12], S3);
            atomicAdd(&acc[13], S4);
#pragma unroll
            for (int b = 14; b < NQ; b++)
                atomicAdd(&acc[b], ((blockIdx.x >> (b - 14)) & 1) ? -P : P);
        }
        __syncthreads();
        if (t < NQ) atomicAdd(&out[NQ - 1 - t], acc[t]);
    }
#undef CF
#undef SF
}

// ---------------------------------------------------------------- launch
extern "C" void kernel_launch(void* const* d_in, const int* in_sizes, int n_in,
                              void* d_out, int out_size) {
    const float* feat = (const float*)d_in[0];
    const float* adj = (const float*)d_in[1];
    const float* params = (const float*)d_in[2];
    float* out = (float*)d_out;

    const int SMEM = LOWDIM * (int)sizeof(float);   // 65536
    cudaFuncSetAttribute(k_passL<1, true,  false>, cudaFuncAttributeMaxDynamicSharedMemorySize, SMEM);
    cudaFuncSetAttribute(k_passHH<1, 2>,           cudaFuncAttributeMaxDynamicSharedMemorySize, SMEM);
    cudaFuncSetAttribute(k_passL<2, false, false>, cudaFuncAttributeMaxDynamicSharedMemorySize, SMEM);
    cudaFuncSetAttribute(k_passH1<3>,              cudaFuncAttributeMaxDynamicSharedMemorySize, SMEM);
    cudaFuncSetAttribute(k_passL<3, false, true>,  cudaFuncAttributeMaxDynamicSharedMemorySize, SMEM);

    k_setup<<<1, 128>>>(feat, adj, params, out);

    k_passL<1, true,  false><<<DIM / LOWDIM, 512, SMEM>>>(out);
    k_passHH<1, 2>          <<<LOWDIM / 64, 512, SMEM>>>();
    k_passL<2, false, false><<<DIM / LOWDIM, 512, SMEM>>>(out);
    k_passH1<3>             <<<LOWDIM / 64, 512, SMEM>>>();
    k_passL<3, false, true> <<<DIM / LOWDIM, 512, SMEM>>>(out);
}